// round 5
// baseline (speedup 1.0000x reference)
#include <cuda_runtime.h>
#include <cstdint>

#define B_SZ 512
#define A_SZ 1024
#define XDIM 1024
#define NREL 500
#define MN (512 * 512)

// scratch (device globals; no allocation allowed)
__device__ float g_X1p[8 * MN];   // gemm1 split-K partials
__device__ float g_X1[MN];        // relu(sum X1p + b1)
__device__ float g_X2p[4 * MN];   // gemm2 split-K partials (bias NOT added)
__device__ float g_relSp[4 * MN]; // relS split-K partials

__device__ __forceinline__ float4 ld4(const float* p) { return *(const float4*)p; }

__device__ __forceinline__ uint64_t pack2(float lo, float hi) {
    uint64_t r; asm("mov.b64 %0, {%1, %2};" : "=l"(r) : "f"(lo), "f"(hi)); return r;
}
__device__ __forceinline__ void unpack2(uint64_t v, float& lo, float& hi) {
    asm("mov.b64 {%0, %1}, %2;" : "=f"(lo), "=f"(hi) : "l"(v));
}
__device__ __forceinline__ void fma2(uint64_t& acc, uint64_t a, uint64_t b) {
    asm("fma.rn.f32x2 %0, %1, %2, %0;" : "+l"(acc) : "l"(a), "l"(b));
}

// ---------------------------------------------------------------------------
// f32x2 GEMM core: 64x64 tile, BK=16, 128 threads, 8m x 4n per thread.
// A pairs along m (natural LDS.64), B duplicated in smem ((b,b) pairs).
// ---------------------------------------------------------------------------
struct GemmSmem {
    float As[16][64];
    float Bs2[16][128];
};

template<typename ALOAD>
__device__ __forceinline__ void gemm_core(
    GemmSmem& sm, ALOAD aload,
    const float* __restrict__ Bm, int ldb, int NB,
    float* __restrict__ C, int kbeg, int kend, int n0, int m0) {
    const int t = threadIdx.x;
    const int r = t & 63;            // row within tile (fill)
    const int kb = (t >> 6) * 8;     // k sub-offset (fill)
    const int tx = t & 15;           // n group
    const int ty = t >> 4;           // m group (0..7)

    uint64_t acc[4][4];
    #pragma unroll
    for (int i = 0; i < 4; i++)
        #pragma unroll
        for (int j = 0; j < 4; j++) acc[i][j] = 0ull;

    for (int k0 = kbeg; k0 < kend; k0 += 16) {
        // A fill: rows m0+r, k = k0+kb .. +7
        float4 a0 = aload(m0 + r, k0 + kb);
        float4 a1 = aload(m0 + r, k0 + kb + 4);
        sm.As[kb + 0][r] = a0.x; sm.As[kb + 1][r] = a0.y;
        sm.As[kb + 2][r] = a0.z; sm.As[kb + 3][r] = a0.w;
        sm.As[kb + 4][r] = a1.x; sm.As[kb + 5][r] = a1.y;
        sm.As[kb + 6][r] = a1.z; sm.As[kb + 7][r] = a1.w;
        // B fill (duplicated pairs): row n0+r
        float4 b0 = make_float4(0.f, 0.f, 0.f, 0.f), b1 = b0;
        if (n0 + r < NB) {
            b0 = ld4(Bm + (size_t)(n0 + r) * ldb + k0 + kb);
            b1 = ld4(Bm + (size_t)(n0 + r) * ldb + k0 + kb + 4);
        }
        *(uint64_t*)&sm.Bs2[kb + 0][2 * r] = pack2(b0.x, b0.x);
        *(uint64_t*)&sm.Bs2[kb + 1][2 * r] = pack2(b0.y, b0.y);
        *(uint64_t*)&sm.Bs2[kb + 2][2 * r] = pack2(b0.z, b0.z);
        *(uint64_t*)&sm.Bs2[kb + 3][2 * r] = pack2(b0.w, b0.w);
        *(uint64_t*)&sm.Bs2[kb + 4][2 * r] = pack2(b1.x, b1.x);
        *(uint64_t*)&sm.Bs2[kb + 5][2 * r] = pack2(b1.y, b1.y);
        *(uint64_t*)&sm.Bs2[kb + 6][2 * r] = pack2(b1.z, b1.z);
        *(uint64_t*)&sm.Bs2[kb + 7][2 * r] = pack2(b1.w, b1.w);
        __syncthreads();

        #pragma unroll
        for (int kk = 0; kk < 16; kk++) {
            uint64_t av[4], bv[4];
            #pragma unroll
            for (int i = 0; i < 4; i++)
                av[i] = *(const uint64_t*)&sm.As[kk][ty * 8 + 2 * i];
            #pragma unroll
            for (int j = 0; j < 4; j++)
                bv[j] = *(const uint64_t*)&sm.Bs2[kk][(tx * 4 + j) * 2];
            #pragma unroll
            for (int i = 0; i < 4; i++)
                #pragma unroll
                for (int j = 0; j < 4; j++)
                    fma2(acc[i][j], av[i], bv[j]);
        }
        __syncthreads();
    }

    // epilogue: 8 rows (pairs) x 4 cols
    #pragma unroll
    for (int i = 0; i < 4; i++) {
        float lo[4], hi[4];
        #pragma unroll
        for (int j = 0; j < 4; j++) unpack2(acc[i][j], lo[j], hi[j]);
        int m = m0 + ty * 8 + 2 * i;
        *(float4*)&C[(size_t)m * 512 + n0 + tx * 4] =
            make_float4(lo[0], lo[1], lo[2], lo[3]);
        *(float4*)&C[(size_t)(m + 1) * 512 + n0 + tx * 4] =
            make_float4(hi[0], hi[1], hi[2], hi[3]);
    }
}

// ---------------------------------------------------------------------------
// GEMM1 (concat fused): X1p[z] = seg(z) @ W1^T chunk. grid (8, 8, 8).
// z in 0..7 selects k range [z*128, z*128+128): 0-1 e_t, 2-5 H, 6-7 r_q.
// ---------------------------------------------------------------------------
__global__ void __launch_bounds__(128, 6) gemm1_fused(
    const float* __restrict__ e_t, const float* __restrict__ Hs,
    const float* __restrict__ r_q, const float* __restrict__ W1) {
    __shared__ GemmSmem sm;
    int z = blockIdx.z;
    const float* A; int lda, colb;
    if (z < 2)      { A = e_t; lda = 256; colb = z * 128; }
    else if (z < 6) { A = Hs;  lda = 512; colb = (z - 2) * 128; }
    else            { A = r_q; lda = 256; colb = (z - 6) * 128; }
    int kbeg = z * 128;
    auto aload = [&](int m, int k) -> float4 {
        return ld4(A + (size_t)m * lda + colb + (k - kbeg));
    };
    gemm_core(sm, aload, W1, XDIM, 512, g_X1p + (size_t)z * MN,
              kbeg, kbeg + 128, blockIdx.x * 64, blockIdx.y * 64);
}

// ---------------------------------------------------------------------------
// X1 = relu(sum_p X1p[p] + b1)
// ---------------------------------------------------------------------------
__global__ void __launch_bounds__(256) reduce_x1(const float* __restrict__ b1) {
    int i = blockIdx.x * 256 + threadIdx.x;
    float s = 0.f;
    #pragma unroll
    for (int p = 0; p < 8; p++) s += g_X1p[(size_t)p * MN + i];
    s += b1[i & 511];
    g_X1[i] = fmaxf(s, 0.f);
}

// ---------------------------------------------------------------------------
// Generic split-K GEMM (A = sum of APART partials + optional bias).
// ---------------------------------------------------------------------------
template<int APART, bool ABIAS>
__global__ void __launch_bounds__(128, 6) gemm_sk(
    const float* __restrict__ A, const float* __restrict__ Abias, int lda,
    const float* __restrict__ Bm, int ldb, int NB,
    float* __restrict__ Cp, int kchunk) {
    __shared__ GemmSmem sm;
    auto aload = [&](int m, int k) -> float4 {
        float4 v = ld4(A + (size_t)m * lda + k);
        #pragma unroll
        for (int p = 1; p < APART; p++) {
            float4 w = ld4(A + (size_t)p * MN + (size_t)m * lda + k);
            v.x += w.x; v.y += w.y; v.z += w.z; v.w += w.w;
        }
        if (ABIAS) {
            float4 bv = ld4(Abias + k);
            v.x += bv.x; v.y += bv.y; v.z += bv.z; v.w += bv.w;
        }
        return v;
    };
    int kbeg = blockIdx.z * kchunk;
    gemm_core(sm, aload, Bm, ldb, NB, Cp + (size_t)blockIdx.z * MN,
              kbeg, kbeg + kchunk, blockIdx.x * 64, blockIdx.y * 64);
}

// ---------------------------------------------------------------------------
// Threefry-2x32 (20 rounds). JAX partitionable bits = o0 ^ o1, counter (0, i).
// ---------------------------------------------------------------------------
__device__ __forceinline__ uint32_t jax_bits(uint32_t i) {
    uint32_t k0 = 0u, k1 = 42u;
    uint32_t k2 = k0 ^ k1 ^ 0x1BD11BDAu;
    uint32_t x0 = k0, x1 = i + k1;
#define TF_R(r) { x0 += x1; x1 = (x1 << (r)) | (x1 >> (32 - (r))); x1 ^= x0; }
    TF_R(13) TF_R(15) TF_R(26) TF_R(6)   x0 += k1; x1 += k2 + 1u;
    TF_R(17) TF_R(29) TF_R(16) TF_R(24)  x0 += k2; x1 += k0 + 2u;
    TF_R(13) TF_R(15) TF_R(26) TF_R(6)   x0 += k0; x1 += k1 + 3u;
    TF_R(17) TF_R(29) TF_R(16) TF_R(24)  x0 += k1; x1 += k2 + 4u;
    TF_R(13) TF_R(15) TF_R(26) TF_R(6)   x0 += k2; x1 += k0 + 5u;
#undef TF_R
    return x0 ^ x1;
}

__device__ __forceinline__ float dot8(float4 v0, float4 v1, const float* x) {
    return v0.x * x[0] + v0.y * x[1] + v0.z * x[2] + v0.w * x[3]
         + v1.x * x[4] + v1.y * x[5] + v1.z * x[6] + v1.w * x[7];
}

// ---------------------------------------------------------------------------
// Gather + masked softmax + entropy + gumbel argmax. 1 block/row, 512 threads.
// Warp w handles 64 actions, 4 in flight.
// ---------------------------------------------------------------------------
__global__ void __launch_bounds__(512) score_softmax_sample(
    const int* __restrict__ r_space,
    const int* __restrict__ e_space,
    const float* __restrict__ mask,
    const float* __restrict__ ent_emb,
    const float* __restrict__ W2_b,
    float* __restrict__ out) {
    int b = blockIdx.x;
    int tid = threadIdx.x;
    int lane = tid & 31;
    int w = tid >> 5;           // 0..15

    __shared__ float sX2[256];
    __shared__ float sSc[1024];
    __shared__ float sMax[16];
    __shared__ float sSum[16];
    __shared__ float sV[16];
    __shared__ float sE[16];
    __shared__ int   sI[16];

    if (tid < 256) {
        float v = W2_b[256 + tid];
        #pragma unroll
        for (int p = 0; p < 4; p++) v += g_X2p[(size_t)p * MN + b * 512 + 256 + tid];
        sX2[tid] = v;
    }
    __syncthreads();

    float x[8];
    #pragma unroll
    for (int j = 0; j < 8; j++) x[j] = sX2[lane * 8 + j];

    const int base = b * A_SZ;

    // ---- scores (4 actions in flight per warp) ----
    for (int it = 0; it < 64; it += 4) {
        int a0 = w * 64 + it;
        float s[4];
        #pragma unroll
        for (int q = 0; q < 4; q++) {
            int e = e_space[base + a0 + q];
            const float4* ep = (const float4*)(ent_emb + (size_t)e * 256 + lane * 8);
            float4 v0 = ep[0], v1 = ep[1];
            s[q] = dot8(v0, v1, x);
        }
        #pragma unroll
        for (int o = 16; o; o >>= 1) {
            #pragma unroll
            for (int q = 0; q < 4; q++)
                s[q] += __shfl_xor_sync(0xFFFFFFFFu, s[q], o);
        }
        if (lane == 0) {
            #pragma unroll
            for (int q = 0; q < 4; q++) {
                int a = a0 + q;
                int r = r_space[base + a];
                float rs = 0.f;
                #pragma unroll
                for (int p = 0; p < 4; p++) rs += g_relSp[(size_t)p * MN + b * 512 + r];
                sSc[a] = s[q] + rs - (1.0f - mask[base + a]) * 1e9f;
            }
        }
    }
    __syncthreads();

    // ---- max ----
    float mx = -__int_as_float(0x7F800000);
    for (int j = tid; j < 1024; j += 512) mx = fmaxf(mx, sSc[j]);
    #pragma unroll
    for (int o = 16; o; o >>= 1) mx = fmaxf(mx, __shfl_xor_sync(0xFFFFFFFFu, mx, o));
    if (lane == 0) sMax[w] = mx;
    __syncthreads();
    mx = sMax[0];
    #pragma unroll
    for (int i = 1; i < 16; i++) mx = fmaxf(mx, sMax[i]);

    // ---- exp & sum ----
    float sum = 0.f;
    for (int j = tid; j < 1024; j += 512) {
        float e = expf(sSc[j] - mx);
        sSc[j] = e;
        sum += e;
    }
    #pragma unroll
    for (int o = 16; o; o >>= 1) sum += __shfl_xor_sync(0xFFFFFFFFu, sum, o);
    if (lane == 0) sSum[w] = sum;
    __syncthreads();
    float total = 0.f;
    #pragma unroll
    for (int i = 0; i < 16; i++) total += sSum[i];

    // ---- p, entropy, gumbel argmax ----
    float ent = 0.f;
    float bestV = -__int_as_float(0x7F800000);
    int bestI = 0x7FFFFFFF;
    for (int j = tid; j < 1024; j += 512) {
        float p = sSc[j] / total;
        sSc[j] = p;
        out[1536 + base + j] = p;                 // action_dist
        float lp = logf(p + 1e-30f);
        ent += p * lp;
        uint32_t bits = jax_bits((uint32_t)(base + j));
        float f = __uint_as_float((bits >> 9) | 0x3F800000u) - 1.0f;
        float u = fmaxf(f, 1.17549435e-38f);
        float g = -logf(-logf(u));
        float v = lp + g;
        if (v > bestV || (v == bestV && j < bestI)) { bestV = v; bestI = j; }
    }
    #pragma unroll
    for (int o = 16; o; o >>= 1) {
        float ov = __shfl_xor_sync(0xFFFFFFFFu, bestV, o);
        int   oi = __shfl_xor_sync(0xFFFFFFFFu, bestI, o);
        float oe = __shfl_xor_sync(0xFFFFFFFFu, ent, o);
        ent += oe;
        if (ov > bestV || (ov == bestV && oi < bestI)) { bestV = ov; bestI = oi; }
    }
    if (lane == 0) { sV[w] = bestV; sI[w] = bestI; sE[w] = ent; }
    __syncthreads();

    if (tid == 0) {
        float bv = sV[0]; int bi = sI[0]; float te = sE[0];
        #pragma unroll
        for (int i = 1; i < 16; i++) {
            te += sE[i];
            if (sV[i] > bv || (sV[i] == bv && sI[i] < bi)) { bv = sV[i]; bi = sI[i]; }
        }
        out[b]        = sSc[bi];                          // action_prob
        out[512 + b]  = (float)r_space[base + bi];        // next_r
        out[1024 + b] = (float)e_space[base + bi];        // next_e
        out[525824 + b] = -te;                            // entropy
    }
}

// ---------------------------------------------------------------------------
extern "C" void kernel_launch(void* const* d_in, const int* in_sizes, int n_in,
                              void* d_out, int out_size) {
    const float* e_t     = (const float*)d_in[0];
    const float* Hs      = (const float*)d_in[1];
    const float* r_q     = (const float*)d_in[2];
    const int*   r_space = (const int*)d_in[3];
    const int*   e_space = (const int*)d_in[4];
    const float* mask    = (const float*)d_in[5];
    const float* W1_w    = (const float*)d_in[6];
    const float* W1_b    = (const float*)d_in[7];
    const float* W2_w    = (const float*)d_in[8];
    const float* W2_b    = (const float*)d_in[9];
    const float* rel_emb = (const float*)d_in[10];
    const float* ent_emb = (const float*)d_in[11];
    float* out = (float*)d_out;

    float *X1, *X2p, *relSp;
    cudaGetSymbolAddress((void**)&X1,    g_X1);
    cudaGetSymbolAddress((void**)&X2p,   g_X2p);
    cudaGetSymbolAddress((void**)&relSp, g_relSp);

    // X1p[z] = concat @ W1^T  (K=1024, SK=8)
    gemm1_fused<<<dim3(8, 8, 8), 128>>>(e_t, Hs, r_q, W1_w);
    // X1 = relu(sum + b1)
    reduce_x1<<<MN / 256, 256>>>(W1_b);
    // X2p[z] = X1 @ W2^T  (K=512, SK=4; bias folded into consumers)
    gemm_sk<1, false><<<dim3(8, 8, 4), 128>>>(X1, nullptr, 512, W2_w, 512, 512, X2p, 128);
    // relSp[z] = (sum X2p + b2)[:, :256] @ rel_emb^T  (K=256, SK=4)
    gemm_sk<4, true><<<dim3(8, 8, 4), 128>>>(X2p, W2_b, 512, rel_emb, 256, NREL, relSp, 64);
    // gather + softmax + entropy + sample
    score_softmax_sample<<<B_SZ, 512>>>(r_space, e_space, mask, ent_emb, W2_b, out);
}

// round 6
// speedup vs baseline: 1.3313x; 1.3313x over previous
#include <cuda_runtime.h>
#include <cstdint>

#define B_SZ 512
#define A_SZ 1024
#define XDIM 1024
#define NREL 500
#define MN (512 * 512)

// scratch (device globals; no allocation allowed)
__device__ float g_X1p[8 * MN];   // gemm1 split-K partials
__device__ float g_X1[MN];        // relu(sum X1p + b1)
__device__ float g_X2p[8 * MN];   // gemm2 split-K partials (bias NOT added)
__device__ float g_relSp[8 * MN]; // relS split-K partials

__device__ __forceinline__ float4 ld4(const float* p) { return *(const float4*)p; }

// ---------------------------------------------------------------------------
// Classic SIMT SGEMM core: 128x128 tile, BK=8, 256 threads, 8x8 per thread.
// Warp tile 32(m) x 64(n); lanes 4(m) x 8(n). Conflict-free fragment loads.
// Global->reg prefetch of next chunk overlapped with inner product.
// ---------------------------------------------------------------------------
struct SgemmSmem {
    float As[8][128];
    float Bs[8][128];
};

template<typename ALOAD>
__device__ __forceinline__ void sgemm_core(
    SgemmSmem& sm, ALOAD aload,
    const float* __restrict__ Bm, int ldb, int NB,
    float* __restrict__ C, int kbeg, int kchunk, int m0, int n0) {
    const int t = threadIdx.x;
    const int row = t >> 1;          // 0..127  (fill row)
    const int kq  = (t & 1) * 4;     // 0 or 4  (fill k sub-offset)
    const int w = t >> 5;
    const int lane = t & 31;
    const int tm = (w & 3) * 32 + (lane & 3) * 8;   // thread m offset
    const int tn = (w >> 2) * 64 + (lane >> 2) * 8; // thread n offset

    float acc[8][8];
    #pragma unroll
    for (int i = 0; i < 8; i++)
        #pragma unroll
        for (int j = 0; j < 8; j++) acc[i][j] = 0.f;

    // preload chunk 0
    float4 aReg = aload(m0 + row, kbeg + kq);
    float4 bReg = make_float4(0.f, 0.f, 0.f, 0.f);
    if (n0 + row < NB) bReg = ld4(Bm + (size_t)(n0 + row) * ldb + kbeg + kq);

    const int nIter = kchunk >> 3;
    for (int it = 0; it < nIter; it++) {
        sm.As[kq + 0][row] = aReg.x; sm.As[kq + 1][row] = aReg.y;
        sm.As[kq + 2][row] = aReg.z; sm.As[kq + 3][row] = aReg.w;
        sm.Bs[kq + 0][row] = bReg.x; sm.Bs[kq + 1][row] = bReg.y;
        sm.Bs[kq + 2][row] = bReg.z; sm.Bs[kq + 3][row] = bReg.w;
        __syncthreads();

        if (it + 1 < nIter) {
            int k = kbeg + (it + 1) * 8 + kq;
            aReg = aload(m0 + row, k);
            if (n0 + row < NB) bReg = ld4(Bm + (size_t)(n0 + row) * ldb + k);
        }

        #pragma unroll
        for (int kk = 0; kk < 8; kk++) {
            float a[8], b[8];
            *(float4*)&a[0] = *(const float4*)&sm.As[kk][tm];
            *(float4*)&a[4] = *(const float4*)&sm.As[kk][tm + 4];
            *(float4*)&b[0] = *(const float4*)&sm.Bs[kk][tn];
            *(float4*)&b[4] = *(const float4*)&sm.Bs[kk][tn + 4];
            #pragma unroll
            for (int i = 0; i < 8; i++)
                #pragma unroll
                for (int j = 0; j < 8; j++)
                    acc[i][j] = fmaf(a[i], b[j], acc[i][j]);
        }
        __syncthreads();
    }

    #pragma unroll
    for (int i = 0; i < 8; i++) {
        int m = m0 + tm + i;
        *(float4*)&C[(size_t)m * 512 + n0 + tn] =
            make_float4(acc[i][0], acc[i][1], acc[i][2], acc[i][3]);
        *(float4*)&C[(size_t)m * 512 + n0 + tn + 4] =
            make_float4(acc[i][4], acc[i][5], acc[i][6], acc[i][7]);
    }
}

// ---------------------------------------------------------------------------
// GEMM1 (concat fused): X1p[z] = seg(z) @ W1^T chunk. grid (4, 4, 8).
// z selects k range [z*128, z*128+128): z 0-1 e_t, 2-5 H, 6-7 r_q.
// ---------------------------------------------------------------------------
__global__ void __launch_bounds__(256) gemm1_fused(
    const float* __restrict__ e_t, const float* __restrict__ Hs,
    const float* __restrict__ r_q, const float* __restrict__ W1) {
    __shared__ SgemmSmem sm;
    int z = blockIdx.z;
    const float* A; int lda, colb;
    if (z < 2)      { A = e_t; lda = 256; colb = z * 128; }
    else if (z < 6) { A = Hs;  lda = 512; colb = (z - 2) * 128; }
    else            { A = r_q; lda = 256; colb = (z - 6) * 128; }
    int kbeg = z * 128;
    auto aload = [&](int m, int k) -> float4 {
        return ld4(A + (size_t)m * lda + colb + (k - kbeg));
    };
    sgemm_core(sm, aload, W1, XDIM, 512, g_X1p + (size_t)z * MN,
               kbeg, 128, blockIdx.y * 128, blockIdx.x * 128);
}

// ---------------------------------------------------------------------------
// X1 = relu(sum_p X1p[p] + b1)
// ---------------------------------------------------------------------------
__global__ void __launch_bounds__(256) reduce_x1(const float* __restrict__ b1) {
    int i = blockIdx.x * 256 + threadIdx.x;
    float s = 0.f;
    #pragma unroll
    for (int p = 0; p < 8; p++) s += g_X1p[(size_t)p * MN + i];
    s += b1[i & 511];
    g_X1[i] = fmaxf(s, 0.f);
}

// ---------------------------------------------------------------------------
// Generic split-K GEMM (A = sum of APART partials + optional bias).
// ---------------------------------------------------------------------------
template<int APART, bool ABIAS>
__global__ void __launch_bounds__(256) gemm_sk(
    const float* __restrict__ A, const float* __restrict__ Abias, int lda,
    const float* __restrict__ Bm, int ldb, int NB,
    float* __restrict__ Cp, int kchunk) {
    __shared__ SgemmSmem sm;
    auto aload = [&](int m, int k) -> float4 {
        float4 v = ld4(A + (size_t)m * lda + k);
        #pragma unroll
        for (int p = 1; p < APART; p++) {
            float4 u = ld4(A + (size_t)p * MN + (size_t)m * lda + k);
            v.x += u.x; v.y += u.y; v.z += u.z; v.w += u.w;
        }
        if (ABIAS) {
            float4 bv = ld4(Abias + k);
            v.x += bv.x; v.y += bv.y; v.z += bv.z; v.w += bv.w;
        }
        return v;
    };
    sgemm_core(sm, aload, Bm, ldb, NB, Cp + (size_t)blockIdx.z * MN,
               blockIdx.z * kchunk, kchunk, blockIdx.y * 128, blockIdx.x * 128);
}

// ---------------------------------------------------------------------------
// Threefry-2x32 (20 rounds). JAX partitionable bits = o0 ^ o1, counter (0, i).
// ---------------------------------------------------------------------------
__device__ __forceinline__ uint32_t jax_bits(uint32_t i) {
    uint32_t k0 = 0u, k1 = 42u;
    uint32_t k2 = k0 ^ k1 ^ 0x1BD11BDAu;
    uint32_t x0 = k0, x1 = i + k1;
#define TF_R(r) { x0 += x1; x1 = (x1 << (r)) | (x1 >> (32 - (r))); x1 ^= x0; }
    TF_R(13) TF_R(15) TF_R(26) TF_R(6)   x0 += k1; x1 += k2 + 1u;
    TF_R(17) TF_R(29) TF_R(16) TF_R(24)  x0 += k2; x1 += k0 + 2u;
    TF_R(13) TF_R(15) TF_R(26) TF_R(6)   x0 += k0; x1 += k1 + 3u;
    TF_R(17) TF_R(29) TF_R(16) TF_R(24)  x0 += k1; x1 += k2 + 4u;
    TF_R(13) TF_R(15) TF_R(26) TF_R(6)   x0 += k2; x1 += k0 + 5u;
#undef TF_R
    return x0 ^ x1;
}

__device__ __forceinline__ float dot8(float4 v0, float4 v1, const float* x) {
    return v0.x * x[0] + v0.y * x[1] + v0.z * x[2] + v0.w * x[3]
         + v1.x * x[4] + v1.y * x[5] + v1.z * x[6] + v1.w * x[7];
}

// ---------------------------------------------------------------------------
// Gather + masked softmax + entropy + gumbel argmax. 1 block/row, 512 threads.
// relS partials pre-reduced into smem once per row.
// ---------------------------------------------------------------------------
__global__ void __launch_bounds__(512) score_softmax_sample(
    const int* __restrict__ r_space,
    const int* __restrict__ e_space,
    const float* __restrict__ mask,
    const float* __restrict__ ent_emb,
    const float* __restrict__ W2_b,
    float* __restrict__ out) {
    int b = blockIdx.x;
    int tid = threadIdx.x;
    int lane = tid & 31;
    int w = tid >> 5;           // 0..15

    __shared__ float sX2[256];
    __shared__ float sRel[512];
    __shared__ float sSc[1024];
    __shared__ float sMax[16];
    __shared__ float sSum[16];
    __shared__ float sV[16];
    __shared__ float sE[16];
    __shared__ int   sI[16];

    // pre-reduce relS partials (8) for this row
    {
        float v = 0.f;
        #pragma unroll
        for (int p = 0; p < 8; p++) v += g_relSp[(size_t)p * MN + b * 512 + tid];
        sRel[tid] = v;
    }
    if (tid < 256) {
        float v = W2_b[256 + tid];
        #pragma unroll
        for (int p = 0; p < 8; p++) v += g_X2p[(size_t)p * MN + b * 512 + 256 + tid];
        sX2[tid] = v;
    }
    __syncthreads();

    float x[8];
    #pragma unroll
    for (int j = 0; j < 8; j++) x[j] = sX2[lane * 8 + j];

    const int base = b * A_SZ;

    // ---- scores (4 actions in flight per warp) ----
    for (int it = 0; it < 64; it += 4) {
        int a0 = w * 64 + it;
        float s[4];
        #pragma unroll
        for (int q = 0; q < 4; q++) {
            int e = e_space[base + a0 + q];
            const float4* ep = (const float4*)(ent_emb + (size_t)e * 256 + lane * 8);
            float4 v0 = ep[0], v1 = ep[1];
            s[q] = dot8(v0, v1, x);
        }
        #pragma unroll
        for (int o = 16; o; o >>= 1) {
            #pragma unroll
            for (int q = 0; q < 4; q++)
                s[q] += __shfl_xor_sync(0xFFFFFFFFu, s[q], o);
        }
        if (lane == 0) {
            #pragma unroll
            for (int q = 0; q < 4; q++) {
                int a = a0 + q;
                int r = r_space[base + a];
                sSc[a] = s[q] + sRel[r] - (1.0f - mask[base + a]) * 1e9f;
            }
        }
    }
    __syncthreads();

    // ---- max ----
    float mx = -__int_as_float(0x7F800000);
    for (int j = tid; j < 1024; j += 512) mx = fmaxf(mx, sSc[j]);
    #pragma unroll
    for (int o = 16; o; o >>= 1) mx = fmaxf(mx, __shfl_xor_sync(0xFFFFFFFFu, mx, o));
    if (lane == 0) sMax[w] = mx;
    __syncthreads();
    mx = sMax[0];
    #pragma unroll
    for (int i = 1; i < 16; i++) mx = fmaxf(mx, sMax[i]);

    // ---- exp & sum ----
    float sum = 0.f;
    for (int j = tid; j < 1024; j += 512) {
        float e = expf(sSc[j] - mx);
        sSc[j] = e;
        sum += e;
    }
    #pragma unroll
    for (int o = 16; o; o >>= 1) sum += __shfl_xor_sync(0xFFFFFFFFu, sum, o);
    if (lane == 0) sSum[w] = sum;
    __syncthreads();
    float total = 0.f;
    #pragma unroll
    for (int i = 0; i < 16; i++) total += sSum[i];

    // ---- p, entropy, gumbel argmax ----
    float ent = 0.f;
    float bestV = -__int_as_float(0x7F800000);
    int bestI = 0x7FFFFFFF;
    for (int j = tid; j < 1024; j += 512) {
        float p = sSc[j] / total;
        sSc[j] = p;
        out[1536 + base + j] = p;                 // action_dist
        float lp = logf(p + 1e-30f);
        ent += p * lp;
        uint32_t bits = jax_bits((uint32_t)(base + j));
        float f = __uint_as_float((bits >> 9) | 0x3F800000u) - 1.0f;
        float u = fmaxf(f, 1.17549435e-38f);
        float g = -logf(-logf(u));
        float v = lp + g;
        if (v > bestV || (v == bestV && j < bestI)) { bestV = v; bestI = j; }
    }
    #pragma unroll
    for (int o = 16; o; o >>= 1) {
        float ov = __shfl_xor_sync(0xFFFFFFFFu, bestV, o);
        int   oi = __shfl_xor_sync(0xFFFFFFFFu, bestI, o);
        float oe = __shfl_xor_sync(0xFFFFFFFFu, ent, o);
        ent += oe;
        if (ov > bestV || (ov == bestV && oi < bestI)) { bestV = ov; bestI = oi; }
    }
    if (lane == 0) { sV[w] = bestV; sI[w] = bestI; sE[w] = ent; }
    __syncthreads();

    if (tid == 0) {
        float bv = sV[0]; int bi = sI[0]; float te = sE[0];
        #pragma unroll
        for (int i = 1; i < 16; i++) {
            te += sE[i];
            if (sV[i] > bv || (sV[i] == bv && sI[i] < bi)) { bv = sV[i]; bi = sI[i]; }
        }
        out[b]        = sSc[bi];                          // action_prob
        out[512 + b]  = (float)r_space[base + bi];        // next_r
        out[1024 + b] = (float)e_space[base + bi];        // next_e
        out[525824 + b] = -te;                            // entropy
    }
}

// ---------------------------------------------------------------------------
extern "C" void kernel_launch(void* const* d_in, const int* in_sizes, int n_in,
                              void* d_out, int out_size) {
    const float* e_t     = (const float*)d_in[0];
    const float* Hs      = (const float*)d_in[1];
    const float* r_q     = (const float*)d_in[2];
    const int*   r_space = (const int*)d_in[3];
    const int*   e_space = (const int*)d_in[4];
    const float* mask    = (const float*)d_in[5];
    const float* W1_w    = (const float*)d_in[6];
    const float* W1_b    = (const float*)d_in[7];
    const float* W2_w    = (const float*)d_in[8];
    const float* W2_b    = (const float*)d_in[9];
    const float* rel_emb = (const float*)d_in[10];
    const float* ent_emb = (const float*)d_in[11];
    float* out = (float*)d_out;

    float *X1, *X2p, *relSp;
    cudaGetSymbolAddress((void**)&X1,    g_X1);
    cudaGetSymbolAddress((void**)&X2p,   g_X2p);
    cudaGetSymbolAddress((void**)&relSp, g_relSp);

    // X1p[z] = concat @ W1^T  (K=1024, SK=8, chunk 128)
    gemm1_fused<<<dim3(4, 4, 8), 256>>>(e_t, Hs, r_q, W1_w);
    // X1 = relu(sum + b1)
    reduce_x1<<<MN / 256, 256>>>(W1_b);
    // X2p[z] = X1 @ W2^T  (K=512, SK=8, chunk 64; bias folded into consumers)
    gemm_sk<1, false><<<dim3(4, 4, 8), 256>>>(X1, nullptr, 512, W2_w, 512, 512, X2p, 64);
    // relSp[z] = (sum X2p + b2)[:, :256] @ rel_emb^T  (K=256, SK=8, chunk 32)
    gemm_sk<8, true><<<dim3(4, 4, 8), 256>>>(X2p, W2_b, 512, rel_emb, 256, NREL, relSp, 32);
    // gather + softmax + entropy + sample
    score_softmax_sample<<<B_SZ, 512>>>(r_space, e_space, mask, ent_emb, W2_b, out);
}